// round 16
// baseline (speedup 1.0000x reference)
#include <cuda_runtime.h>
#include <stdint.h>
#include <math.h>

#define Bb 2
#define Hh 16
#define Ss 2048
#define Dd 64

__device__ float g_invl[Bb * Hh * Ss];

#define LDE 72                 // padded smem row length (fp16 elems)
#define ROWB (LDE * 2)         // 144 bytes per row
// kernel A smem: Q plane, K plane, mask
#define A_OFF_Q 0
#define A_OFF_K (A_OFF_Q + 128 * ROWB)
#define A_OFF_MASK (A_OFF_K + 128 * ROWB)
#define A_SMEM (A_OFF_MASK + 512)
// kernel B smem: Q, K, V planes, mask
#define OFF_QH 0
#define OFF_KH (OFF_QH + 128 * ROWB)
#define OFF_VH (OFF_KH + 128 * ROWB)
#define OFF_MASK (OFF_VH + 128 * ROWB)
#define SMEM_TOT (OFF_MASK + 512)

__device__ __forceinline__ uint32_t smem_u32(const void* p) {
    uint32_t a;
    asm("{ .reg .u64 t; cvta.to.shared.u64 t, %1; cvt.u32.u64 %0, t; }" : "=r"(a) : "l"(p));
    return a;
}
__device__ __forceinline__ uint32_t pack16(float a, float b) {
    uint32_t r;
    asm("cvt.rn.f16x2.f32 %0, %1, %2;" : "=r"(r) : "f"(b), "f"(a));
    return r;
}
__device__ __forceinline__ void ldsm4(uint32_t (&r)[4], uint32_t a) {
    asm volatile("ldmatrix.sync.aligned.m8n8.x4.shared.b16 {%0,%1,%2,%3}, [%4];"
                 : "=r"(r[0]), "=r"(r[1]), "=r"(r[2]), "=r"(r[3]) : "r"(a));
}
__device__ __forceinline__ void ldsm4t(uint32_t& r0, uint32_t& r1, uint32_t& r2, uint32_t& r3,
                                       uint32_t a) {
    asm volatile("ldmatrix.sync.aligned.m8n8.x4.trans.shared.b16 {%0,%1,%2,%3}, [%4];"
                 : "=r"(r0), "=r"(r1), "=r"(r2), "=r"(r3) : "r"(a));
}
__device__ __forceinline__ void mma16816(float (&c)[4], const uint32_t (&a)[4],
                                         uint32_t b0, uint32_t b1) {
    asm volatile("mma.sync.aligned.m16n8k16.row.col.f32.f16.f16.f32 "
                 "{%0,%1,%2,%3}, {%4,%5,%6,%7}, {%8,%9}, {%0,%1,%2,%3};"
                 : "+f"(c[0]), "+f"(c[1]), "+f"(c[2]), "+f"(c[3])
                 : "r"(a[0]), "r"(a[1]), "r"(a[2]), "r"(a[3]), "r"(b0), "r"(b1));
}
__device__ __forceinline__ void prefetchL2(const void* p) {
    asm volatile("prefetch.global.L2 [%0];" ::"l"(p));
}
__device__ __forceinline__ void stcs2(float* p, float2 v) {
    asm volatile("st.global.cs.v2.f32 [%0], {%1,%2};" ::"l"(p), "f"(v.x), "f"(v.y));
}
__device__ __forceinline__ void stcs4(float* p, float4 v) {
    asm volatile("st.global.cs.v4.f32 [%0], {%1,%2,%3,%4};"
                 ::"l"(p), "f"(v.x), "f"(v.y), "f"(v.z), "f"(v.w));
}

// Quad-local repack: lo_pair = row cols kb+2t..+1, hi_pair = cols kb+8+2t..+1.
// Returns float4 = cols kb+4t .. kb+4t+3 (contiguous) via 2-round butterfly.
__device__ __forceinline__ float4 repack4(float2 lo_pair, float2 hi_pair, int t) {
    float2 z = (t < 2) ? hi_pair : lo_pair;           // send the "other" half
    float2 r;
    r.x = __shfl_xor_sync(0xffffffffu, z.x, 2);
    r.y = __shfl_xor_sync(0xffffffffu, z.y, 2);
    float2 o = (t < 2) ? lo_pair : hi_pair;
    bool selr = (t == 0) || (t == 3);
    float2 s = selr ? r : o;
    float2 sr;
    sr.x = __shfl_xor_sync(0xffffffffu, s.x, 1);
    sr.y = __shfl_xor_sync(0xffffffffu, s.y, 1);
    float2 lo4, hi4;
    if (t == 0)      { lo4 = o;  hi4 = sr; }
    else if (t == 1) { lo4 = sr; hi4 = r;  }
    else if (t == 2) { lo4 = r;  hi4 = sr; }
    else             { lo4 = sr; hi4 = o;  }
    return make_float4(lo4.x, lo4.y, hi4.x, hi4.y);
}

// ================= Kernel A: row sums (MMA1 + exp only, high occupancy) =================
__global__ __launch_bounds__(256, 4)
void attn_sums(const float* __restrict__ Q, const float* __restrict__ K,
               const int* __restrict__ M)
{
    const int bid = blockIdx.x;
    const int tid = threadIdx.x;
    extern __shared__ char smc[];
    const uint32_t smb = smem_u32(smc);
    const int w = tid >> 5;
    const int lane = tid & 31;
    const int g = lane >> 2;
    const int t = lane & 3;
    const int l15 = lane & 15;

    const int bh = bid >> 4;
    const int b = bh / Hh;
    const int q0 = (bid & 15) * 128;

    const float* Qg = Q + ((size_t)bh * Ss + q0) * Dd;
    const float* Kg = K + (size_t)bh * Ss * Dd;
    const int* Mg = M + (size_t)b * Ss;
    float* maskS = (float*)(smc + A_OFF_MASK);

    for (int i = tid; i < 2048; i += 256) {
        int row = i >> 4;
        int d4 = (i & 15) << 2;
        float4 v = *(const float4*)(Qg + (size_t)row * Dd + d4);
        v.x *= 0.125f; v.y *= 0.125f; v.z *= 0.125f; v.w *= 0.125f;
        *(uint2*)(smc + A_OFF_Q + row * ROWB + d4 * 2) =
            make_uint2(pack16(v.x, v.y), pack16(v.z, v.w));
    }
    __syncthreads();

    uint32_t qh[4][4];
    {
        uint32_t abase = smb + (uint32_t)(w * 16 + l15) * ROWB + ((lane >> 4) * 8) * 2;
        #pragma unroll
        for (int ks = 0; ks < 4; ++ks)
            ldsm4(qh[ks], abase + A_OFF_Q + ks * 32);
    }
    const uint32_t kaddr = smb + A_OFF_K +
        (uint32_t)((lane & 7) + ((lane >> 4) & 1) * 8) * ROWB + ((lane >> 3) & 1) * 16;

    float lp0 = 0.f, lp1 = 0.f;
    for (int kt = 0; kt < Ss / 128; ++kt) {
        const int k0 = kt * 128;
        __syncthreads();
        for (int i = tid; i < 2048; i += 256) {
            int row = i >> 4;
            int d4 = (i & 15) << 2;
            float4 v = *(const float4*)(Kg + (size_t)(k0 + row) * Dd + d4);
            *(uint2*)(smc + A_OFF_K + row * ROWB + d4 * 2) =
                make_uint2(pack16(v.x, v.y), pack16(v.z, v.w));
        }
        if (tid < 128) maskS[tid] = Mg[k0 + tid] ? 0.f : 1.f;
        if (kt + 1 < Ss / 128)
            prefetchL2(Kg + (size_t)(k0 + 128) * Dd + tid * 32);
        __syncthreads();

        #pragma unroll 2
        for (int ch = 0; ch < 8; ++ch) {
            const int kb = ch * 16;
            float s0[4] = {0.f, 0.f, 0.f, 0.f};
            float s1[4] = {0.f, 0.f, 0.f, 0.f};
            const uint32_t ka = kaddr + (uint32_t)kb * ROWB;
            #pragma unroll
            for (int ks = 0; ks < 4; ++ks) {
                uint32_t kr[4];
                ldsm4(kr, ka + ks * 32);
                mma16816(s0, qh[ks], kr[0], kr[1]);
                mma16816(s1, qh[ks], kr[2], kr[3]);
            }
            float m00 = maskS[kb + 2 * t];
            float m01 = maskS[kb + 2 * t + 1];
            float m10 = maskS[kb + 8 + 2 * t];
            float m11 = maskS[kb + 8 + 2 * t + 1];
            lp0 += (m00 * __expf(s0[0]) + m01 * __expf(s0[1])) +
                   (m10 * __expf(s1[0]) + m11 * __expf(s1[1]));
            lp1 += (m00 * __expf(s0[2]) + m01 * __expf(s0[3])) +
                   (m10 * __expf(s1[2]) + m11 * __expf(s1[3]));
        }
    }
    lp0 += __shfl_xor_sync(0xffffffffu, lp0, 1);
    lp0 += __shfl_xor_sync(0xffffffffu, lp0, 2);
    lp1 += __shfl_xor_sync(0xffffffffu, lp1, 1);
    lp1 += __shfl_xor_sync(0xffffffffu, lp1, 2);
    if (t == 0) {
        const int r0 = q0 + w * 16 + g;
        g_invl[(size_t)bh * Ss + r0]     = 1.f / lp0;
        g_invl[(size_t)bh * Ss + r0 + 8] = 1.f / lp1;
    }
}

// ====== Kernel B: recompute scores, write normalized att (float4) + MMA2 ======
__global__ __launch_bounds__(256, 2)
void attn_write(const float* __restrict__ Q, const float* __restrict__ K,
                const float* __restrict__ V, const int* __restrict__ M,
                float* __restrict__ att, float* __restrict__ outv)
{
    const int bid = blockIdx.x;
    const int tid = threadIdx.x;
    extern __shared__ char smc[];
    const uint32_t smb = smem_u32(smc);
    const int w = tid >> 5;
    const int lane = tid & 31;
    const int g = lane >> 2;
    const int t = lane & 3;
    const int l15 = lane & 15;

    const int bh = bid >> 4;
    const int b = bh / Hh;
    const int q0 = (bid & 15) * 128;

    const float* Qg = Q + ((size_t)bh * Ss + q0) * Dd;
    const float* Kg = K + (size_t)bh * Ss * Dd;
    const float* Vg = V + (size_t)bh * Ss * Dd;
    float* Ag = att + (size_t)bh * Ss * Ss;
    const int* Mg = M + (size_t)b * Ss;
    float* maskS = (float*)(smc + OFF_MASK);

    for (int i = tid; i < 2048; i += 256) {
        int row = i >> 4;
        int d4 = (i & 15) << 2;
        float4 v = *(const float4*)(Qg + (size_t)row * Dd + d4);
        v.x *= 0.125f; v.y *= 0.125f; v.z *= 0.125f; v.w *= 0.125f;
        *(uint2*)(smc + OFF_QH + row * ROWB + d4 * 2) =
            make_uint2(pack16(v.x, v.y), pack16(v.z, v.w));
    }
    __syncthreads();

    uint32_t qh[4][4];
    {
        uint32_t abase = smb + (uint32_t)(w * 16 + l15) * ROWB + ((lane >> 4) * 8) * 2;
        #pragma unroll
        for (int ks = 0; ks < 4; ++ks)
            ldsm4(qh[ks], abase + OFF_QH + ks * 32);
    }
    const uint32_t kaddr = smb + OFF_KH +
        (uint32_t)((lane & 7) + ((lane >> 4) & 1) * 8) * ROWB + ((lane >> 3) & 1) * 16;
    const uint32_t vaddr = smb + OFF_VH + (uint32_t)l15 * ROWB + ((lane >> 4) & 1) * 16;

    const int r0 = q0 + w * 16 + g;
    const float inv0 = __ldg(&g_invl[(size_t)bh * Ss + r0]);
    const float inv1 = __ldg(&g_invl[(size_t)bh * Ss + r0 + 8]);

    float o[8][4];
    #pragma unroll
    for (int i = 0; i < 8; ++i)
        #pragma unroll
        for (int j = 0; j < 4; ++j) o[i][j] = 0.f;

    for (int kt = 0; kt < Ss / 128; ++kt) {
        const int k0 = kt * 128;
        __syncthreads();
        for (int i = tid; i < 2048; i += 256) {
            int row = i >> 4;
            int d4 = (i & 15) << 2;
            float4 v = *(const float4*)(Kg + (size_t)(k0 + row) * Dd + d4);
            *(uint2*)(smc + OFF_KH + row * ROWB + d4 * 2) =
                make_uint2(pack16(v.x, v.y), pack16(v.z, v.w));
            float4 u = *(const float4*)(Vg + (size_t)(k0 + row) * Dd + d4);
            *(uint2*)(smc + OFF_VH + row * ROWB + d4 * 2) =
                make_uint2(pack16(u.x, u.y), pack16(u.z, u.w));
        }
        if (tid < 128) maskS[tid] = Mg[k0 + tid] ? 0.f : 1.f;
        if (kt + 1 < Ss / 128) {
            prefetchL2(Kg + (size_t)(k0 + 128) * Dd + tid * 32);
            prefetchL2(Vg + (size_t)(k0 + 128) * Dd + tid * 32);
        }
        __syncthreads();

        for (int ch = 0; ch < 8; ++ch) {
            const int kb = ch * 16;

            // ---- MMA1 (identical fragments/order to kernel A -> identical e) ----
            float s0[4] = {0.f, 0.f, 0.f, 0.f};
            float s1[4] = {0.f, 0.f, 0.f, 0.f};
            const uint32_t ka = kaddr + (uint32_t)kb * ROWB;
            #pragma unroll
            for (int ks = 0; ks < 4; ++ks) {
                uint32_t kr[4];
                ldsm4(kr, ka + ks * 32);
                mma16816(s0, qh[ks], kr[0], kr[1]);
                mma16816(s1, qh[ks], kr[2], kr[3]);
            }

            float m00 = maskS[kb + 2 * t];
            float m01 = maskS[kb + 2 * t + 1];
            float m10 = maskS[kb + 8 + 2 * t];
            float m11 = maskS[kb + 8 + 2 * t + 1];
            float p00 = inv0 * (m00 * __expf(s0[0]));
            float p01 = inv0 * (m01 * __expf(s0[1]));
            float p02 = inv1 * (m00 * __expf(s0[2]));
            float p03 = inv1 * (m01 * __expf(s0[3]));
            float p10 = inv0 * (m10 * __expf(s1[0]));
            float p11 = inv0 * (m11 * __expf(s1[1]));
            float p12 = inv1 * (m10 * __expf(s1[2]));
            float p13 = inv1 * (m11 * __expf(s1[3]));

            // ---- repack to contiguous float4 per lane; 2 STG.128 per thread ----
            const int c4 = k0 + kb + 4 * t;
            float4 fa = repack4(make_float2(p00, p01), make_float2(p10, p11), t);
            float4 fb = repack4(make_float2(p02, p03), make_float2(p12, p13), t);
            stcs4(Ag + (size_t)r0 * Ss + c4, fa);
            stcs4(Ag + (size_t)(r0 + 8) * Ss + c4, fb);

            // ---- P fragments from NORMALIZED p ----
            uint32_t ph[4];
            ph[0] = pack16(p00, p01);
            ph[1] = pack16(p02, p03);
            ph[2] = pack16(p10, p11);
            ph[3] = pack16(p12, p13);

            // ---- MMA2: O += Phi * Vhi ----
            const uint32_t va = vaddr + (uint32_t)kb * ROWB;
            #pragma unroll
            for (int np = 0; np < 4; ++np) {
                uint32_t v0, v1, v2, v3;
                ldsm4t(v0, v1, v2, v3, va + np * 32);
                mma16816(o[2 * np], ph, v0, v1);
                mma16816(o[2 * np + 1], ph, v2, v3);
            }
        }
    }

    // ---- O already normalized: store directly ----
    float* O0 = outv + ((size_t)bh * Ss + r0) * Dd;
    float* O1 = O0 + 8 * Dd;
    #pragma unroll
    for (int nb2 = 0; nb2 < 8; ++nb2) {
        stcs2(O0 + nb2 * 8 + 2 * t, make_float2(o[nb2][0], o[nb2][1]));
        stcs2(O1 + nb2 * 8 + 2 * t, make_float2(o[nb2][2], o[nb2][3]));
    }
}

extern "C" void kernel_launch(void* const* d_in, const int* in_sizes, int n_in,
                              void* d_out, int out_size)
{
    const float* Q = (const float*)d_in[0];
    const float* K = (const float*)d_in[1];
    const float* V = (const float*)d_in[2];
    const int* M = (const int*)d_in[3];

    float* att = (float*)d_out;
    float* sumv = att + (size_t)Bb * Hh * Ss * Ss;

    static int configured = 0;
    if (!configured) {
        cudaFuncSetAttribute(attn_sums, cudaFuncAttributeMaxDynamicSharedMemorySize, A_SMEM);
        cudaFuncSetAttribute(attn_write, cudaFuncAttributeMaxDynamicSharedMemorySize, SMEM_TOT);
        configured = 1;
    }

    attn_sums<<<Bb * Hh * 16, 256, A_SMEM>>>(Q, K, M);
    attn_write<<<Bb * Hh * 16, 256, SMEM_TOT>>>(Q, K, V, M, att, sumv);
}